// round 13
// baseline (speedup 1.0000x reference)
#include <cuda_runtime.h>
#include <cuda_bf16.h>
#include <math.h>
#include <stdint.h>

// Problem constants
#define Bc    8
#define Nc    9856
#define Dc    256
#define HEADS 8
#define HD    32
#define WH    7
#define WW    11
#define L77   77
#define HIDc  512
#define Hc    56
#define Wc    176
#define NH    8
#define NWn   16
#define MROWS (Bc * Nc)       // 78848
#define NWIN  (Bc * NH * NWn) // 1024

// Tiled image layout: tile (rb=r/128, kt=k/64) is an 8192-elem (16 KB) block at
// ((rb*(K/64))+kt)*8192; row r%128 = 64 elems (128 B); 16B chunk c at (c ^ (row&7)).
// Rows 0..63 of a tile are its first contiguous 8 KB.

// ---------------------------------------------------------------------------
// Scratch (device globals)
// ---------------------------------------------------------------------------
__device__ __nv_bfloat16 g_xnb[(size_t)MROWS * Dc];        // xn image; later o image
__device__ __nv_bfloat16 g_qkvb[(size_t)MROWS * 3 * Dc];   // qkv row-major; later [yn img | hmid img]
__device__ float         g_y[(size_t)MROWS * Dc];          // x + attn residual
__device__ __nv_bfloat16 g_wqkv[3 * Dc * Dc];
__device__ __nv_bfloat16 g_wout[Dc * Dc];
__device__ __nv_bfloat16 g_wfc1[HIDc * Dc];
__device__ __nv_bfloat16 g_wfc2[Dc * HIDc];

// ---------------------------------------------------------------------------
// helpers
// ---------------------------------------------------------------------------
__device__ __forceinline__ uint32_t packbf(float a, float b)
{
    union { __nv_bfloat162 h; uint32_t u; } p;
    p.h = __float22bfloat162_rn(make_float2(a, b));
    return p.u;
}

__device__ __forceinline__ void ldsm4(uint32_t* r, uint32_t addr)
{
    asm volatile("ldmatrix.sync.aligned.m8n8.x4.shared.b16 {%0,%1,%2,%3}, [%4];"
                 : "=r"(r[0]), "=r"(r[1]), "=r"(r[2]), "=r"(r[3]) : "r"(addr));
}

__device__ __forceinline__ void ldsm4t(uint32_t* r, uint32_t addr)
{
    asm volatile("ldmatrix.sync.aligned.m8n8.x4.trans.shared.b16 {%0,%1,%2,%3}, [%4];"
                 : "=r"(r[0]), "=r"(r[1]), "=r"(r[2]), "=r"(r[3]) : "r"(addr));
}

__device__ __forceinline__ void mma_bf16(float (&c)[4], const uint32_t* a,
                                         uint32_t b0, uint32_t b1)
{
    asm volatile(
        "mma.sync.aligned.m16n8k16.row.col.f32.bf16.bf16.f32 "
        "{%0,%1,%2,%3}, {%4,%5,%6,%7}, {%8,%9}, {%0,%1,%2,%3};"
        : "+f"(c[0]), "+f"(c[1]), "+f"(c[2]), "+f"(c[3])
        : "r"(a[0]), "r"(a[1]), "r"(a[2]), "r"(a[3]), "r"(b0), "r"(b1));
}

__device__ __forceinline__ float gelu_exact(float v)
{
    return 0.5f * v * (1.0f + erff(v * 0.70710678118654752f));
}

__device__ __forceinline__ void mbar_init(uint32_t a, uint32_t cnt)
{
    asm volatile("mbarrier.init.shared.b64 [%0], %1;" :: "r"(a), "r"(cnt) : "memory");
}
__device__ __forceinline__ void mbar_expect_tx(uint32_t a, uint32_t bytes)
{
    asm volatile("mbarrier.arrive.expect_tx.shared.b64 _, [%0], %1;"
                 :: "r"(a), "r"(bytes) : "memory");
}
__device__ __forceinline__ void mbar_wait(uint32_t a, uint32_t ph)
{
    asm volatile(
        "{\n\t.reg .pred P;\n"
        "LW%=:\n\tmbarrier.try_wait.parity.acquire.cta.shared::cta.b64 P, [%0], %1, 0x989680;\n"
        "\t@P bra LD%=;\n\tbra LW%=;\nLD%=:\n\t}"
        :: "r"(a), "r"(ph) : "memory");
}
__device__ __forceinline__ void bulk_g2s(uint32_t dst, const void* src,
                                         uint32_t bytes, uint32_t mbar)
{
    asm volatile(
        "cp.async.bulk.shared::cluster.global.mbarrier::complete_tx::bytes "
        "[%0], [%1], %2, [%3];"
        :: "r"(dst), "l"(src), "r"(bytes), "r"(mbar) : "memory");
}

// ---------------------------------------------------------------------------
// weight conversion helper (fp32 row-major [N,K] -> tiled bf16 image)
// ---------------------------------------------------------------------------
__device__ __forceinline__ void emit_w(const float* __restrict__ src,
                                       __nv_bfloat16* __restrict__ dst,
                                       int i, int Kd)
{
    int n = i / Kd, k = i - n * Kd;
    float4 v0 = *(const float4*)(src + i);
    float4 v1 = *(const float4*)(src + i + 4);
    union { __nv_bfloat162 h[4]; uint4 u; } pk;
    pk.h[0] = __float22bfloat162_rn(make_float2(v0.x, v0.y));
    pk.h[1] = __float22bfloat162_rn(make_float2(v0.z, v0.w));
    pk.h[2] = __float22bfloat162_rn(make_float2(v1.x, v1.y));
    pk.h[3] = __float22bfloat162_rn(make_float2(v1.z, v1.w));
    int KT = Kd >> 6;
    size_t e = ((size_t)((n >> 7) * KT + (k >> 6))) * 8192 + (n & 127) * 64
             + ((((k >> 3) & 7) ^ (n & 7)) << 3);
    *(uint4*)(dst + e) = pk.u;
}

// ---------------------------------------------------------------------------
// LayerNorm body (one warp per row of 256; writes tiled bf16 image, KT=4)
// ---------------------------------------------------------------------------
__device__ __forceinline__ void ln_row(const float* __restrict__ x,
                                       const float* __restrict__ g,
                                       const float* __restrict__ b,
                                       __nv_bfloat16* __restrict__ out,
                                       size_t row, int lane)
{
    const float* xr = x + row * Dc;
    int c = lane * 8;
    float4 v0 = *(const float4*)(xr + c);
    float4 v1 = *(const float4*)(xr + c + 4);
    float sum = v0.x + v0.y + v0.z + v0.w + v1.x + v1.y + v1.z + v1.w;
    float sq  = v0.x*v0.x + v0.y*v0.y + v0.z*v0.z + v0.w*v0.w
              + v1.x*v1.x + v1.y*v1.y + v1.z*v1.z + v1.w*v1.w;
    #pragma unroll
    for (int off = 16; off; off >>= 1) {
        sum += __shfl_xor_sync(0xffffffff, sum, off);
        sq  += __shfl_xor_sync(0xffffffff, sq,  off);
    }
    float mu  = sum * (1.0f / 256.0f);
    float var = sq * (1.0f / 256.0f) - mu * mu;
    float rs  = rsqrtf(var + 1e-5f);
    float4 g0 = *(const float4*)(g + c), g1 = *(const float4*)(g + c + 4);
    float4 b0 = *(const float4*)(b + c), b1 = *(const float4*)(b + c + 4);
    union { __nv_bfloat162 h[4]; uint4 u; } pk;
    pk.h[0] = __float22bfloat162_rn(make_float2((v0.x - mu) * rs * g0.x + b0.x,
                                                (v0.y - mu) * rs * g0.y + b0.y));
    pk.h[1] = __float22bfloat162_rn(make_float2((v0.z - mu) * rs * g0.z + b0.z,
                                                (v0.w - mu) * rs * g0.w + b0.w));
    pk.h[2] = __float22bfloat162_rn(make_float2((v1.x - mu) * rs * g1.x + b1.x,
                                                (v1.y - mu) * rs * g1.y + b1.y));
    pk.h[3] = __float22bfloat162_rn(make_float2((v1.z - mu) * rs * g1.z + b1.z,
                                                (v1.w - mu) * rs * g1.w + b1.w));
    int kt = lane >> 3;
    int cs = (lane & 7) ^ ((int)row & 7);
    size_t e = ((size_t)((row >> 7) * 4 + kt)) * 8192 + (row & 127) * 64 + (cs << 3);
    *(uint4*)(out + e) = pk.u;
}

__global__ void __launch_bounds__(256) ln_bf_kernel(const float* __restrict__ x,
                                                    const float* __restrict__ g,
                                                    const float* __restrict__ b,
                                                    __nv_bfloat16* __restrict__ out)
{
    int warp = threadIdx.x >> 5, lane = threadIdx.x & 31;
    ln_row(x, g, b, out, (size_t)blockIdx.x * 8 + warp, lane);
}

// Merged: blocks [0,256) convert the 4 weight matrices; blocks [256,...) do LN1.
__global__ void __launch_bounds__(256) prep_kernel(const float* __restrict__ x,
                                                   const float* __restrict__ g,
                                                   const float* __restrict__ b,
                                                   __nv_bfloat16* __restrict__ out,
                                                   const float* __restrict__ w0,
                                                   const float* __restrict__ w1,
                                                   const float* __restrict__ w2,
                                                   const float* __restrict__ w3,
                                                   __nv_bfloat16* __restrict__ o0,
                                                   __nv_bfloat16* __restrict__ o1,
                                                   __nv_bfloat16* __restrict__ o2,
                                                   __nv_bfloat16* __restrict__ o3)
{
    if (blockIdx.x < 256) {
        int u = blockIdx.x * 256 + threadIdx.x;
        if (u < 24576)      emit_w(w0, o0, u * 8, 256);
        else if (u < 32768) emit_w(w1, o1, (u - 24576) * 8, 256);
        else if (u < 49152) emit_w(w2, o2, (u - 32768) * 8, 256);
        else                emit_w(w3, o3, (u - 49152) * 8, 512);
        return;
    }
    int warp = threadIdx.x >> 5, lane = threadIdx.x & 31;
    ln_row(x, g, b, out, (size_t)(blockIdx.x - 256) * 8 + warp, lane);
}

// ---------------------------------------------------------------------------
// bf16 GEMM on tiled images: CTA 128x64, BK=64, 3-stage bulk ring (24KB/stage:
// A 16KB + B 8KB half-tile). 8 warps in 4x2 grid, warp tile 32x32 -> 3 CTAs/SM.
// Sync scheme: R10-proven (data mbar wait -> mma -> __syncthreads -> tid0 refill).
// ---------------------------------------------------------------------------
#define BSTG 24576u
#define BGSMEM (3 * 24576)

template <int EPI, int OBF, int K, int OTILED, int OKT>
__global__ void __launch_bounds__(256, 3) bgemm_kernel(const __nv_bfloat16* __restrict__ Aimg,
                                                       const __nv_bfloat16* __restrict__ Bimg,
                                                       const float* __restrict__ bias,
                                                       const float* __restrict__ resid,
                                                       void* __restrict__ Cv,
                                                       int M, int N)
{
    extern __shared__ __nv_bfloat16 dyn[];
    __shared__ uint64_t mbar_s[3];

    constexpr int KT = K >> 6;
    int tid = threadIdx.x, lane = tid & 31, warp = tid >> 5;
    int wm = warp >> 1, wn = warp & 1;       // 4 x 2 warp grid
    int m0 = blockIdx.y * 128, n0 = blockIdx.x * 64;

    uint32_t sbase = (uint32_t)__cvta_generic_to_shared(dyn);
    uint32_t mbD = (uint32_t)__cvta_generic_to_shared(&mbar_s[0]);

    const __nv_bfloat16* Asrc = Aimg + (size_t)blockIdx.y * KT * 8192;
    // B: 64-row slice = contiguous 8KB half of a 128-row image tile
    const __nv_bfloat16* Bsrc = Bimg + ((size_t)(n0 >> 7) * KT) * 8192
                              + (size_t)((n0 >> 6) & 1) * 4096;

    if (tid == 0) {
        mbar_init(mbD, 1);
        mbar_init(mbD + 8, 1);
        mbar_init(mbD + 16, 1);
    }
    __syncthreads();
    if (tid == 0) {
        #pragma unroll
        for (int s = 0; s < 3 && s < KT; s++) {
            mbar_expect_tx(mbD + s * 8, 24576);
            bulk_g2s(sbase + s * BSTG,         Asrc + s * 8192, 16384, mbD + s * 8);
            bulk_g2s(sbase + s * BSTG + 16384, Bsrc + s * 8192, 8192,  mbD + s * 8);
        }
    }

    int ac = lane >> 4;            // A chunk select
    int br = (lane & 7) | (((lane >> 4) & 1) << 3);
    int bc = (lane >> 3) & 1;      // B chunk select
    int sk = lane & 7;
    uint32_t aRow[2], bRow[2];
    #pragma unroll
    for (int mt = 0; mt < 2; mt++)
        aRow[mt] = (wm * 32 + mt * 16 + (lane & 15)) * 128;
    #pragma unroll
    for (int p = 0; p < 2; p++)
        bRow[p] = (wn * 32 + p * 16 + br) * 128;

    float acc[2][4][4] = {};

    #pragma unroll
    for (int kt = 0; kt < KT; kt++) {
        const int s = kt % 3;
        const uint32_t ph = (kt / 3) & 1;
        mbar_wait(mbD + s * 8, ph);
        uint32_t aB = sbase + s * BSTG;
        uint32_t bB = aB + 16384;
        #pragma unroll
        for (int kk = 0; kk < 4; kk++) {
            uint32_t ca = (uint32_t)(((kk * 2 + ac) ^ sk) << 4);
            uint32_t cb = (uint32_t)(((kk * 2 + bc) ^ sk) << 4);
            uint32_t a[2][4], b[2][4];
            #pragma unroll
            for (int mt = 0; mt < 2; mt++)
                ldsm4(a[mt], aB + aRow[mt] + ca);
            #pragma unroll
            for (int p = 0; p < 2; p++)
                ldsm4(b[p], bB + bRow[p] + cb);
            #pragma unroll
            for (int mt = 0; mt < 2; mt++) {
                mma_bf16(acc[mt][0], a[mt], b[0][0], b[0][1]);
                mma_bf16(acc[mt][1], a[mt], b[0][2], b[0][3]);
                mma_bf16(acc[mt][2], a[mt], b[1][0], b[1][1]);
                mma_bf16(acc[mt][3], a[mt], b[1][2], b[1][3]);
            }
        }
        __syncthreads();
        if (tid == 0 && kt + 3 < KT) {
            mbar_expect_tx(mbD + s * 8, 24576);
            bulk_g2s(sbase + s * BSTG,         Asrc + (kt + 3) * 8192, 16384, mbD + s * 8);
            bulk_g2s(sbase + s * BSTG + 16384, Bsrc + (kt + 3) * 8192, 8192,  mbD + s * 8);
        }
    }

    float* Cf = (float*)Cv;
    __nv_bfloat16* Cb = (__nv_bfloat16*)Cv;
    int g = lane >> 2, t = lane & 3;
    #pragma unroll
    for (int mt = 0; mt < 2; mt++) {
        size_t r0 = (size_t)m0 + wm * 32 + mt * 16 + g;
        size_t r1 = r0 + 8;
        #pragma unroll
        for (int nt = 0; nt < 4; nt++) {
            int col = n0 + wn * 32 + nt * 8 + 2 * t;
            float b0 = bias[col], b1 = bias[col + 1];
            float v00 = acc[mt][nt][0] + b0, v01 = acc[mt][nt][1] + b1;
            float v10 = acc[mt][nt][2] + b0, v11 = acc[mt][nt][3] + b1;
            if (EPI == 1) {
                v00 = gelu_exact(v00); v01 = gelu_exact(v01);
                v10 = gelu_exact(v10); v11 = gelu_exact(v11);
            }
            if (EPI == 2) {
                float2 q0 = *(const float2*)&resid[r0 * N + col];
                float2 q1 = *(const float2*)&resid[r1 * N + col];
                v00 += q0.x; v01 += q0.y; v10 += q1.x; v11 += q1.y;
            }
            if (OTILED) {
                int kto = col >> 6;
                int ci  = (col >> 3) & 7;
                size_t e0 = ((size_t)((r0 >> 7) * OKT + kto)) * 8192 + (r0 & 127) * 64
                          + (((size_t)(ci ^ ((int)r0 & 7))) << 3) + (col & 7);
                size_t e1 = ((size_t)((r1 >> 7) * OKT + kto)) * 8192 + (r1 & 127) * 64
                          + (((size_t)(ci ^ ((int)r1 & 7))) << 3) + (col & 7);
                *(uint32_t*)&Cb[e0] = packbf(v00, v01);
                *(uint32_t*)&Cb[e1] = packbf(v10, v11);
            } else if (OBF) {
                *(uint32_t*)&Cb[r0 * N + col] = packbf(v00, v01);
                *(uint32_t*)&Cb[r1 * N + col] = packbf(v10, v11);
            } else {
                *(float2*)&Cf[r0 * N + col] = make_float2(v00, v01);
                *(float2*)&Cf[r1 * N + col] = make_float2(v10, v11);
            }
        }
    }
}

// ---------------------------------------------------------------------------
// Windowed attention (bf16 mma.sync) — unchanged
// ---------------------------------------------------------------------------
__device__ __forceinline__ int rowmap(int wi, int l)
{
    int b   = wi >> 7;
    int rem = wi & 127;
    int hb  = rem >> 4;
    int wb  = rem & 15;
    int r   = l / WW;
    int c   = l - r * WW;
    return b * Nc + (hb * WH + r) * Wc + wb * WW + c;
}

__global__ void __launch_bounds__(160) attn_kernel(const __nv_bfloat16* __restrict__ qkv,
                                                   __nv_bfloat16* __restrict__ o)
{
    __shared__ __nv_bfloat16 sQ[80 * 40];
    __shared__ __nv_bfloat16 sK[80 * 40];
    __shared__ __nv_bfloat16 sV[80 * 40];

    int bx = blockIdx.x, wi = bx >> 3, h = bx & 7;
    int tid = threadIdx.x, lane = tid & 31, w = tid >> 5;

    int lrow = tid >> 2, lseg = tid & 3;
    #pragma unroll
    for (int r0 = 0; r0 < 80; r0 += 40) {
        int l = r0 + lrow;
        uint4 qv = make_uint4(0, 0, 0, 0), kv = qv, vv = qv;
        if (l < L77) {
            int grow = rowmap(wi, l);
            const __nv_bfloat16* base = qkv + (size_t)grow * (3 * Dc) + h * HD + lseg * 8;
            qv = *(const uint4*)(base);
            kv = *(const uint4*)(base + Dc);
            vv = *(const uint4*)(base + 2 * Dc);
        }
        *(uint4*)&sQ[l * 40 + lseg * 8] = qv;
        *(uint4*)&sK[l * 40 + lseg * 8] = kv;
        *(uint4*)&sV[l * 40 + lseg * 8] = vv;
    }
    __syncthreads();

    int a_row = lane & 15;
    int a_c   = lane >> 4;
    int b_row = (lane & 7) | (((lane >> 4) & 1) << 3);
    int b_c   = (lane >> 3) & 1;
    int g = lane >> 2, t = lane & 3;

    uint32_t aQ = (uint32_t)__cvta_generic_to_shared(&sQ[(w * 16 + a_row) * 40]) + a_c * 16;
    uint32_t bK = (uint32_t)__cvta_generic_to_shared(&sK[b_row * 40]) + b_c * 16;
    uint32_t bV = (uint32_t)__cvta_generic_to_shared(sV)
                + ((lane & 15) * 40 + ((lane >> 4) << 3)) * 2;

    float s[10][4] = {};
    uint32_t aq[2][4];
    ldsm4(aq[0], aQ);
    ldsm4(aq[1], aQ + 32);
    #pragma unroll
    for (int kk = 0; kk < 2; kk++) {
        #pragma unroll
        for (int p = 0; p < 5; p++) {
            uint32_t b[4];
            ldsm4(b, bK + p * 1280 + kk * 32);
            mma_bf16(s[2 * p],     aq[kk], b[0], b[1]);
            mma_bf16(s[2 * p + 1], aq[kk], b[2], b[3]);
        }
    }

    if (72 + 2 * t >= L77) { s[9][0] = -1e30f; s[9][2] = -1e30f; }
    if (73 + 2 * t >= L77) { s[9][1] = -1e30f; s[9][3] = -1e30f; }

    const float scale = 0.17677669529663687f;
    float mx0 = -1e30f, mx1 = -1e30f;
    #pragma unroll
    for (int nt = 0; nt < 10; nt++) {
        mx0 = fmaxf(mx0, fmaxf(s[nt][0], s[nt][1]));
        mx1 = fmaxf(mx1, fmaxf(s[nt][2], s[nt][3]));
    }
    mx0 = fmaxf(mx0, __shfl_xor_sync(0xffffffff, mx0, 1));
    mx0 = fmaxf(mx0, __shfl_xor_sync(0xffffffff, mx0, 2));
    mx1 = fmaxf(mx1, __shfl_xor_sync(0xffffffff, mx1, 1));
    mx1 = fmaxf(mx1, __shfl_xor_sync(0xffffffff, mx1, 2));
    float ms0 = mx0 * scale, ms1 = mx1 * scale;

    float e[10][4];
    float sum0 = 0.f, sum1 = 0.f;
    #pragma unroll
    for (int nt = 0; nt < 10; nt++) {
        e[nt][0] = __expf(fmaf(s[nt][0], scale, -ms0));
        e[nt][1] = __expf(fmaf(s[nt][1], scale, -ms0));
        e[nt][2] = __expf(fmaf(s[nt][2], scale, -ms1));
        e[nt][3] = __expf(fmaf(s[nt][3], scale, -ms1));
        sum0 += e[nt][0] + e[nt][1];
        sum1 += e[nt][2] + e[nt][3];
    }
    sum0 += __shfl_xor_sync(0xffffffff, sum0, 1);
    sum0 += __shfl_xor_sync(0xffffffff, sum0, 2);
    sum1 += __shfl_xor_sync(0xffffffff, sum1, 1);
    sum1 += __shfl_xor_sync(0xffffffff, sum1, 2);
    float inv0 = 1.0f / sum0, inv1 = 1.0f / sum1;

    uint32_t pa[5][4];
    #pragma unroll
    for (int kf = 0; kf < 5; kf++) {
        pa[kf][0] = packbf(e[2 * kf][0],     e[2 * kf][1]);
        pa[kf][1] = packbf(e[2 * kf][2],     e[2 * kf][3]);
        pa[kf][2] = packbf(e[2 * kf + 1][0], e[2 * kf + 1][1]);
        pa[kf][3] = packbf(e[2 * kf + 1][2], e[2 * kf + 1][3]);
    }

    float oa[4][4] = {};
    #pragma unroll
    for (int kf = 0; kf < 5; kf++) {
        #pragma unroll
        for (int vt = 0; vt < 2; vt++) {
            uint32_t b[4];
            ldsm4t(b, bV + (kf * 16 * 40 + vt * 16) * 2);
            mma_bf16(oa[2 * vt],     pa[kf], b[0], b[1]);
            mma_bf16(oa[2 * vt + 1], pa[kf], b[2], b[3]);
        }
    }

    int r0 = w * 16 + g, r1 = r0 + 8;
    if (r0 < L77) {
        int grow = rowmap(wi, r0);
        size_t base = ((size_t)((grow >> 7) * 4 + (h >> 1))) * 8192 + (grow & 127) * 64;
        int rk = grow & 7;
        #pragma unroll
        for (int nt = 0; nt < 4; nt++) {
            int ci = ((h & 1) * 4 + nt) ^ rk;
            *(uint32_t*)&o[base + ci * 8 + 2 * t] =
                packbf(oa[nt][0] * inv0, oa[nt][1] * inv0);
        }
    }
    if (r1 < L77) {
        int grow = rowmap(wi, r1);
        size_t base = ((size_t)((grow >> 7) * 4 + (h >> 1))) * 8192 + (grow & 127) * 64;
        int rk = grow & 7;
        #pragma unroll
        for (int nt = 0; nt < 4; nt++) {
            int ci = ((h & 1) * 4 + nt) ^ rk;
            *(uint32_t*)&o[base + ci * 8 + 2 * t] =
                packbf(oa[nt][2] * inv1, oa[nt][3] * inv1);
        }
    }
}

// ---------------------------------------------------------------------------
// Launch
// ---------------------------------------------------------------------------
extern "C" void kernel_launch(void* const* d_in, const int* in_sizes, int n_in,
                              void* d_out, int out_size)
{
    const float* x         = (const float*)d_in[0];
    const float* norm1_g   = (const float*)d_in[1];
    const float* norm1_b   = (const float*)d_in[2];
    const float* in_proj_w = (const float*)d_in[3];
    const float* in_proj_b = (const float*)d_in[4];
    const float* out_w     = (const float*)d_in[5];
    const float* out_b     = (const float*)d_in[6];
    const float* norm2_g   = (const float*)d_in[7];
    const float* norm2_b   = (const float*)d_in[8];
    const float* fc1_w     = (const float*)d_in[9];
    const float* fc1_b     = (const float*)d_in[10];
    const float* fc2_w     = (const float*)d_in[11];
    const float* fc2_b     = (const float*)d_in[12];
    float* out = (float*)d_out;

    __nv_bfloat16 *p_xnb, *p_qkvb, *p_wqkv, *p_wout, *p_wfc1, *p_wfc2;
    float* p_y;
    cudaGetSymbolAddress((void**)&p_xnb,  g_xnb);
    cudaGetSymbolAddress((void**)&p_qkvb, g_qkvb);
    cudaGetSymbolAddress((void**)&p_y,    g_y);
    cudaGetSymbolAddress((void**)&p_wqkv, g_wqkv);
    cudaGetSymbolAddress((void**)&p_wout, g_wout);
    cudaGetSymbolAddress((void**)&p_wfc1, g_wfc1);
    cudaGetSymbolAddress((void**)&p_wfc2, g_wfc2);

    cudaFuncSetAttribute((const void*)bgemm_kernel<0, 1, 256, 0, 0>,
                         cudaFuncAttributeMaxDynamicSharedMemorySize, BGSMEM);
    cudaFuncSetAttribute((const void*)bgemm_kernel<2, 0, 256, 0, 0>,
                         cudaFuncAttributeMaxDynamicSharedMemorySize, BGSMEM);
    cudaFuncSetAttribute((const void*)bgemm_kernel<1, 1, 256, 1, 8>,
                         cudaFuncAttributeMaxDynamicSharedMemorySize, BGSMEM);
    cudaFuncSetAttribute((const void*)bgemm_kernel<2, 0, 512, 0, 0>,
                         cudaFuncAttributeMaxDynamicSharedMemorySize, BGSMEM);

    // 0+1) weights -> tiled bf16 images AND LN1 (merged)
    prep_kernel<<<256 + MROWS / 8, 256>>>(x, norm1_g, norm1_b, p_xnb,
                                          in_proj_w, out_w, fc1_w, fc2_w,
                                          p_wqkv, p_wout, p_wfc1, p_wfc2);

    // 2) QKV = xn @ Wqkv^T + b  (row-major bf16)
    {
        dim3 grid(768 / 64, MROWS / 128);
        bgemm_kernel<0, 1, 256, 0, 0><<<grid, 256, BGSMEM>>>(
            p_xnb, p_wqkv, in_proj_b, nullptr, p_qkvb, MROWS, 3 * Dc);
    }

    // 3) attention -> o image (reuse g_xnb)
    attn_kernel<<<NWIN * HEADS, 160>>>(p_qkvb, p_xnb);

    // 4) y = x + o @ Wout^T + b  (fp32 row-major)
    {
        dim3 grid(Dc / 64, MROWS / 128);
        bgemm_kernel<2, 0, 256, 0, 0><<<grid, 256, BGSMEM>>>(
            p_xnb, p_wout, out_b, x, p_y, MROWS, Dc);
    }

    // 5) LN2: y -> yn image (into g_qkvb[0 : M*256))
    ln_bf_kernel<<<MROWS / 8, 256>>>(p_y, norm2_g, norm2_b, p_qkvb);

    // 6) hmid = gelu(yn @ Wfc1^T + b)  (tiled image, OKT=8)
    __nv_bfloat16* p_yn   = p_qkvb;
    __nv_bfloat16* p_hmid = p_qkvb + (size_t)MROWS * Dc;
    {
        dim3 grid(HIDc / 64, MROWS / 128);
        bgemm_kernel<1, 1, 256, 1, 8><<<grid, 256, BGSMEM>>>(
            p_yn, p_wfc1, fc1_b, nullptr, p_hmid, MROWS, HIDc);
    }

    // 7) out = y + hmid @ Wfc2^T + b  (fp32 row-major)
    {
        dim3 grid(Dc / 64, MROWS / 128);
        bgemm_kernel<2, 0, 512, 0, 0><<<grid, 256, BGSMEM>>>(
            p_hmid, p_wfc2, fc2_b, p_y, out, MROWS, Dc);
    }
}

// round 14
// speedup vs baseline: 1.0646x; 1.0646x over previous
#include <cuda_runtime.h>
#include <cuda_bf16.h>
#include <math.h>
#include <stdint.h>

// Problem constants
#define Bc    8
#define Nc    9856
#define Dc    256
#define HEADS 8
#define HD    32
#define WH    7
#define WW    11
#define L77   77
#define HIDc  512
#define Hc    56
#define Wc    176
#define NH    8
#define NWn   16
#define MROWS (Bc * Nc)       // 78848
#define NWIN  (Bc * NH * NWn) // 1024

// Tiled image layout: tile (rb=r/128, kt=k/64) is an 8192-elem (16 KB) block at
// ((rb*(K/64))+kt)*8192; row r%128 = 64 elems (128 B); 16B chunk c at (c ^ (row&7)).

// ---------------------------------------------------------------------------
// Scratch (device globals)
// ---------------------------------------------------------------------------
__device__ __nv_bfloat16 g_xnb[(size_t)MROWS * Dc];        // xn image; later o image
__device__ __nv_bfloat16 g_qkvb[(size_t)MROWS * 3 * Dc];   // qkv row-major; later [yn img | hmid img]
__device__ float         g_y[(size_t)MROWS * Dc];          // x + attn residual
__device__ __nv_bfloat16 g_wqkv[3 * Dc * Dc];
__device__ __nv_bfloat16 g_wout[Dc * Dc];
__device__ __nv_bfloat16 g_wfc1[HIDc * Dc];
__device__ __nv_bfloat16 g_wfc2[Dc * HIDc];

// ---------------------------------------------------------------------------
// helpers
// ---------------------------------------------------------------------------
__device__ __forceinline__ uint32_t packbf(float a, float b)
{
    union { __nv_bfloat162 h; uint32_t u; } p;
    p.h = __float22bfloat162_rn(make_float2(a, b));
    return p.u;
}

__device__ __forceinline__ void ldsm4(uint32_t* r, uint32_t addr)
{
    asm volatile("ldmatrix.sync.aligned.m8n8.x4.shared.b16 {%0,%1,%2,%3}, [%4];"
                 : "=r"(r[0]), "=r"(r[1]), "=r"(r[2]), "=r"(r[3]) : "r"(addr));
}

__device__ __forceinline__ void ldsm4t(uint32_t* r, uint32_t addr)
{
    asm volatile("ldmatrix.sync.aligned.m8n8.x4.trans.shared.b16 {%0,%1,%2,%3}, [%4];"
                 : "=r"(r[0]), "=r"(r[1]), "=r"(r[2]), "=r"(r[3]) : "r"(addr));
}

__device__ __forceinline__ void mma_bf16(float (&c)[4], const uint32_t* a,
                                         uint32_t b0, uint32_t b1)
{
    asm volatile(
        "mma.sync.aligned.m16n8k16.row.col.f32.bf16.bf16.f32 "
        "{%0,%1,%2,%3}, {%4,%5,%6,%7}, {%8,%9}, {%0,%1,%2,%3};"
        : "+f"(c[0]), "+f"(c[1]), "+f"(c[2]), "+f"(c[3])
        : "r"(a[0]), "r"(a[1]), "r"(a[2]), "r"(a[3]), "r"(b0), "r"(b1));
}

__device__ __forceinline__ float gelu_exact(float v)
{
    return 0.5f * v * (1.0f + erff(v * 0.70710678118654752f));
}

__device__ __forceinline__ void mbar_init(uint32_t a, uint32_t cnt)
{
    asm volatile("mbarrier.init.shared.b64 [%0], %1;" :: "r"(a), "r"(cnt) : "memory");
}
__device__ __forceinline__ void mbar_expect_tx(uint32_t a, uint32_t bytes)
{
    asm volatile("mbarrier.arrive.expect_tx.shared.b64 _, [%0], %1;"
                 :: "r"(a), "r"(bytes) : "memory");
}
__device__ __forceinline__ void mbar_wait(uint32_t a, uint32_t ph)
{
    asm volatile(
        "{\n\t.reg .pred P;\n"
        "LW%=:\n\tmbarrier.try_wait.parity.acquire.cta.shared::cta.b64 P, [%0], %1, 0x989680;\n"
        "\t@P bra LD%=;\n\tbra LW%=;\nLD%=:\n\t}"
        :: "r"(a), "r"(ph) : "memory");
}
__device__ __forceinline__ void bulk_g2s(uint32_t dst, const void* src,
                                         uint32_t bytes, uint32_t mbar)
{
    asm volatile(
        "cp.async.bulk.shared::cluster.global.mbarrier::complete_tx::bytes "
        "[%0], [%1], %2, [%3];"
        :: "r"(dst), "l"(src), "r"(bytes), "r"(mbar) : "memory");
}

// ---------------------------------------------------------------------------
// weight conversion helper (fp32 row-major [N,K] -> tiled bf16 image)
// ---------------------------------------------------------------------------
__device__ __forceinline__ void emit_w(const float* __restrict__ src,
                                       __nv_bfloat16* __restrict__ dst,
                                       int i, int Kd)
{
    int n = i / Kd, k = i - n * Kd;
    float4 v0 = *(const float4*)(src + i);
    float4 v1 = *(const float4*)(src + i + 4);
    union { __nv_bfloat162 h[4]; uint4 u; } pk;
    pk.h[0] = __float22bfloat162_rn(make_float2(v0.x, v0.y));
    pk.h[1] = __float22bfloat162_rn(make_float2(v0.z, v0.w));
    pk.h[2] = __float22bfloat162_rn(make_float2(v1.x, v1.y));
    pk.h[3] = __float22bfloat162_rn(make_float2(v1.z, v1.w));
    int KT = Kd >> 6;
    size_t e = ((size_t)((n >> 7) * KT + (k >> 6))) * 8192 + (n & 127) * 64
             + ((((k >> 3) & 7) ^ (n & 7)) << 3);
    *(uint4*)(dst + e) = pk.u;
}

// ---------------------------------------------------------------------------
// LayerNorm body (one warp per row of 256; writes tiled bf16 image, KT=4)
// ---------------------------------------------------------------------------
__device__ __forceinline__ void ln_row(const float* __restrict__ x,
                                       const float* __restrict__ g,
                                       const float* __restrict__ b,
                                       __nv_bfloat16* __restrict__ out,
                                       size_t row, int lane)
{
    const float* xr = x + row * Dc;
    int c = lane * 8;
    float4 v0 = *(const float4*)(xr + c);
    float4 v1 = *(const float4*)(xr + c + 4);
    float sum = v0.x + v0.y + v0.z + v0.w + v1.x + v1.y + v1.z + v1.w;
    float sq  = v0.x*v0.x + v0.y*v0.y + v0.z*v0.z + v0.w*v0.w
              + v1.x*v1.x + v1.y*v1.y + v1.z*v1.z + v1.w*v1.w;
    #pragma unroll
    for (int off = 16; off; off >>= 1) {
        sum += __shfl_xor_sync(0xffffffff, sum, off);
        sq  += __shfl_xor_sync(0xffffffff, sq,  off);
    }
    float mu  = sum * (1.0f / 256.0f);
    float var = sq * (1.0f / 256.0f) - mu * mu;
    float rs  = rsqrtf(var + 1e-5f);
    float4 g0 = *(const float4*)(g + c), g1 = *(const float4*)(g + c + 4);
    float4 b0 = *(const float4*)(b + c), b1 = *(const float4*)(b + c + 4);
    union { __nv_bfloat162 h[4]; uint4 u; } pk;
    pk.h[0] = __float22bfloat162_rn(make_float2((v0.x - mu) * rs * g0.x + b0.x,
                                                (v0.y - mu) * rs * g0.y + b0.y));
    pk.h[1] = __float22bfloat162_rn(make_float2((v0.z - mu) * rs * g0.z + b0.z,
                                                (v0.w - mu) * rs * g0.w + b0.w));
    pk.h[2] = __float22bfloat162_rn(make_float2((v1.x - mu) * rs * g1.x + b1.x,
                                                (v1.y - mu) * rs * g1.y + b1.y));
    pk.h[3] = __float22bfloat162_rn(make_float2((v1.z - mu) * rs * g1.z + b1.z,
                                                (v1.w - mu) * rs * g1.w + b1.w));
    int kt = lane >> 3;
    int cs = (lane & 7) ^ ((int)row & 7);
    size_t e = ((size_t)((row >> 7) * 4 + kt)) * 8192 + (row & 127) * 64 + (cs << 3);
    *(uint4*)(out + e) = pk.u;
}

__global__ void __launch_bounds__(256) ln_bf_kernel(const float* __restrict__ x,
                                                    const float* __restrict__ g,
                                                    const float* __restrict__ b,
                                                    __nv_bfloat16* __restrict__ out)
{
    int warp = threadIdx.x >> 5, lane = threadIdx.x & 31;
    ln_row(x, g, b, out, (size_t)blockIdx.x * 8 + warp, lane);
}

// Merged: blocks [0,256) convert the 4 weight matrices; blocks [256,...) do LN1.
__global__ void __launch_bounds__(256) prep_kernel(const float* __restrict__ x,
                                                   const float* __restrict__ g,
                                                   const float* __restrict__ b,
                                                   __nv_bfloat16* __restrict__ out,
                                                   const float* __restrict__ w0,
                                                   const float* __restrict__ w1,
                                                   const float* __restrict__ w2,
                                                   const float* __restrict__ w3,
                                                   __nv_bfloat16* __restrict__ o0,
                                                   __nv_bfloat16* __restrict__ o1,
                                                   __nv_bfloat16* __restrict__ o2,
                                                   __nv_bfloat16* __restrict__ o3)
{
    if (blockIdx.x < 256) {
        int u = blockIdx.x * 256 + threadIdx.x;
        if (u < 24576)      emit_w(w0, o0, u * 8, 256);
        else if (u < 32768) emit_w(w1, o1, (u - 24576) * 8, 256);
        else if (u < 49152) emit_w(w2, o2, (u - 32768) * 8, 256);
        else                emit_w(w3, o3, (u - 49152) * 8, 512);
        return;
    }
    int warp = threadIdx.x >> 5, lane = threadIdx.x & 31;
    ln_row(x, g, b, out, (size_t)(blockIdx.x - 256) * 8 + warp, lane);
}

// ---------------------------------------------------------------------------
// bf16 GEMM on tiled images (R10 config): CTA 128x128, BK=64, 3-stage bulk
// ring (32 KB/stage). __syncthreads + refill ONLY when a refill is needed
// (kt+3 < KT): 1 sync for K=256, 5 for K=512. Race-free (R10 semantics).
// ---------------------------------------------------------------------------
#define BGSMEM (3 * 32768)

template <int EPI, int OBF, int K, int OTILED, int OKT>
__global__ void __launch_bounds__(256, 2) bgemm_kernel(const __nv_bfloat16* __restrict__ Aimg,
                                                       const __nv_bfloat16* __restrict__ Bimg,
                                                       const float* __restrict__ bias,
                                                       const float* __restrict__ resid,
                                                       void* __restrict__ Cv,
                                                       int M, int N)
{
    extern __shared__ __nv_bfloat16 dyn[];
    __shared__ uint64_t mbar_s[3];

    constexpr int KT = K >> 6;
    int tid = threadIdx.x, lane = tid & 31, warp = tid >> 5;
    int wm = warp >> 2, wn = warp & 3;
    int m0 = blockIdx.y * 128, n0 = blockIdx.x * 128;

    uint32_t sbase = (uint32_t)__cvta_generic_to_shared(dyn);
    uint32_t mb0 = (uint32_t)__cvta_generic_to_shared(&mbar_s[0]);

    const __nv_bfloat16* Asrc = Aimg + (size_t)blockIdx.y * KT * 8192;
    const __nv_bfloat16* Bsrc = Bimg + (size_t)blockIdx.x * KT * 8192;

    if (tid == 0) {
        mbar_init(mb0, 1);
        mbar_init(mb0 + 8, 1);
        mbar_init(mb0 + 16, 1);
    }
    __syncthreads();
    if (tid == 0) {
        #pragma unroll
        for (int s = 0; s < 3 && s < KT; s++) {
            mbar_expect_tx(mb0 + s * 8, 32768);
            bulk_g2s(sbase + s * 32768,         Asrc + s * 8192, 16384, mb0 + s * 8);
            bulk_g2s(sbase + s * 32768 + 16384, Bsrc + s * 8192, 16384, mb0 + s * 8);
        }
    }

    int ac = lane >> 4;            // A chunk select
    int br = (lane & 7) | (((lane >> 4) & 1) << 3);
    int bc = (lane >> 3) & 1;      // B chunk select
    int sk = lane & 7;
    uint32_t aRow[4], bRow[2];
    #pragma unroll
    for (int mt = 0; mt < 4; mt++)
        aRow[mt] = (wm * 64 + mt * 16 + (lane & 15)) * 128;
    #pragma unroll
    for (int p = 0; p < 2; p++)
        bRow[p] = (wn * 32 + p * 16 + br) * 128;

    float acc[4][4][4] = {};

    #pragma unroll
    for (int kt = 0; kt < KT; kt++) {
        const int s = kt % 3;
        mbar_wait(mb0 + s * 8, (kt / 3) & 1);
        uint32_t aB = sbase + s * 32768;
        uint32_t bB = aB + 16384;
        #pragma unroll
        for (int kk = 0; kk < 4; kk++) {
            uint32_t ca = (uint32_t)(((kk * 2 + ac) ^ sk) << 4);
            uint32_t cb = (uint32_t)(((kk * 2 + bc) ^ sk) << 4);
            uint32_t a[4][4], b[2][4];
            #pragma unroll
            for (int mt = 0; mt < 4; mt++)
                ldsm4(a[mt], aB + aRow[mt] + ca);
            #pragma unroll
            for (int p = 0; p < 2; p++)
                ldsm4(b[p], bB + bRow[p] + cb);
            #pragma unroll
            for (int mt = 0; mt < 4; mt++) {
                mma_bf16(acc[mt][0], a[mt], b[0][0], b[0][1]);
                mma_bf16(acc[mt][1], a[mt], b[0][2], b[0][3]);
                mma_bf16(acc[mt][2], a[mt], b[1][0], b[1][1]);
                mma_bf16(acc[mt][3], a[mt], b[1][2], b[1][3]);
            }
        }
        // Sync + refill only when this stage must be recycled.
        if (kt + 3 < KT) {
            __syncthreads();
            if (tid == 0) {
                mbar_expect_tx(mb0 + s * 8, 32768);
                bulk_g2s(sbase + s * 32768,         Asrc + (kt + 3) * 8192, 16384, mb0 + s * 8);
                bulk_g2s(sbase + s * 32768 + 16384, Bsrc + (kt + 3) * 8192, 16384, mb0 + s * 8);
            }
        }
    }

    float* Cf = (float*)Cv;
    __nv_bfloat16* Cb = (__nv_bfloat16*)Cv;
    int g = lane >> 2, t = lane & 3;
    #pragma unroll
    for (int mt = 0; mt < 4; mt++) {
        size_t r0 = (size_t)m0 + wm * 64 + mt * 16 + g;
        size_t r1 = r0 + 8;
        #pragma unroll
        for (int nt = 0; nt < 4; nt++) {
            int col = n0 + wn * 32 + nt * 8 + 2 * t;
            float b0 = bias[col], b1 = bias[col + 1];
            float v00 = acc[mt][nt][0] + b0, v01 = acc[mt][nt][1] + b1;
            float v10 = acc[mt][nt][2] + b0, v11 = acc[mt][nt][3] + b1;
            if (EPI == 1) {
                v00 = gelu_exact(v00); v01 = gelu_exact(v01);
                v10 = gelu_exact(v10); v11 = gelu_exact(v11);
            }
            if (EPI == 2) {
                float2 q0 = *(const float2*)&resid[r0 * N + col];
                float2 q1 = *(const float2*)&resid[r1 * N + col];
                v00 += q0.x; v01 += q0.y; v10 += q1.x; v11 += q1.y;
            }
            if (OTILED) {
                int kto = col >> 6;
                int ci  = (col >> 3) & 7;
                size_t e0 = ((size_t)((r0 >> 7) * OKT + kto)) * 8192 + (r0 & 127) * 64
                          + (((size_t)(ci ^ ((int)r0 & 7))) << 3) + (col & 7);
                size_t e1 = ((size_t)((r1 >> 7) * OKT + kto)) * 8192 + (r1 & 127) * 64
                          + (((size_t)(ci ^ ((int)r1 & 7))) << 3) + (col & 7);
                *(uint32_t*)&Cb[e0] = packbf(v00, v01);
                *(uint32_t*)&Cb[e1] = packbf(v10, v11);
            } else if (OBF) {
                *(uint32_t*)&Cb[r0 * N + col] = packbf(v00, v01);
                *(uint32_t*)&Cb[r1 * N + col] = packbf(v10, v11);
            } else {
                *(float2*)&Cf[r0 * N + col] = make_float2(v00, v01);
                *(float2*)&Cf[r1 * N + col] = make_float2(v10, v11);
            }
        }
    }
}

// ---------------------------------------------------------------------------
// Windowed attention (bf16 mma.sync) — unchanged from R10
// ---------------------------------------------------------------------------
__device__ __forceinline__ int rowmap(int wi, int l)
{
    int b   = wi >> 7;
    int rem = wi & 127;
    int hb  = rem >> 4;
    int wb  = rem & 15;
    int r   = l / WW;
    int c   = l - r * WW;
    return b * Nc + (hb * WH + r) * Wc + wb * WW + c;
}

__global__ void __launch_bounds__(160) attn_kernel(const __nv_bfloat16* __restrict__ qkv,
                                                   __nv_bfloat16* __restrict__ o)
{
    __shared__ __nv_bfloat16 sQ[80 * 40];
    __shared__ __nv_bfloat16 sK[80 * 40];
    __shared__ __nv_bfloat16 sV[80 * 40];

    int bx = blockIdx.x, wi = bx >> 3, h = bx & 7;
    int tid = threadIdx.x, lane = tid & 31, w = tid >> 5;

    int lrow = tid >> 2, lseg = tid & 3;
    #pragma unroll
    for (int r0 = 0; r0 < 80; r0 += 40) {
        int l = r0 + lrow;
        uint4 qv = make_uint4(0, 0, 0, 0), kv = qv, vv = qv;
        if (l < L77) {
            int grow = rowmap(wi, l);
            const __nv_bfloat16* base = qkv + (size_t)grow * (3 * Dc) + h * HD + lseg * 8;
            qv = *(const uint4*)(base);
            kv = *(const uint4*)(base + Dc);
            vv = *(const uint4*)(base + 2 * Dc);
        }
        *(uint4*)&sQ[l * 40 + lseg * 8] = qv;
        *(uint4*)&sK[l * 40 + lseg * 8] = kv;
        *(uint4*)&sV[l * 40 + lseg * 8] = vv;
    }
    __syncthreads();

    int a_row = lane & 15;
    int a_c   = lane >> 4;
    int b_row = (lane & 7) | (((lane >> 4) & 1) << 3);
    int b_c   = (lane >> 3) & 1;
    int g = lane >> 2, t = lane & 3;

    uint32_t aQ = (uint32_t)__cvta_generic_to_shared(&sQ[(w * 16 + a_row) * 40]) + a_c * 16;
    uint32_t bK = (uint32_t)__cvta_generic_to_shared(&sK[b_row * 40]) + b_c * 16;
    uint32_t bV = (uint32_t)__cvta_generic_to_shared(sV)
                + ((lane & 15) * 40 + ((lane >> 4) << 3)) * 2;

    float s[10][4] = {};
    uint32_t aq[2][4];
    ldsm4(aq[0], aQ);
    ldsm4(aq[1], aQ + 32);
    #pragma unroll
    for (int kk = 0; kk < 2; kk++) {
        #pragma unroll
        for (int p = 0; p < 5; p++) {
            uint32_t b[4];
            ldsm4(b, bK + p * 1280 + kk * 32);
            mma_bf16(s[2 * p],     aq[kk], b[0], b[1]);
            mma_bf16(s[2 * p + 1], aq[kk], b[2], b[3]);
        }
    }

    if (72 + 2 * t >= L77) { s[9][0] = -1e30f; s[9][2] = -1e30f; }
    if (73 + 2 * t >= L77) { s[9][1] = -1e30f; s[9][3] = -1e30f; }

    const float scale = 0.17677669529663687f;
    float mx0 = -1e30f, mx1 = -1e30f;
    #pragma unroll
    for (int nt = 0; nt < 10; nt++) {
        mx0 = fmaxf(mx0, fmaxf(s[nt][0], s[nt][1]));
        mx1 = fmaxf(mx1, fmaxf(s[nt][2], s[nt][3]));
    }
    mx0 = fmaxf(mx0, __shfl_xor_sync(0xffffffff, mx0, 1));
    mx0 = fmaxf(mx0, __shfl_xor_sync(0xffffffff, mx0, 2));
    mx1 = fmaxf(mx1, __shfl_xor_sync(0xffffffff, mx1, 1));
    mx1 = fmaxf(mx1, __shfl_xor_sync(0xffffffff, mx1, 2));
    float ms0 = mx0 * scale, ms1 = mx1 * scale;

    float e[10][4];
    float sum0 = 0.f, sum1 = 0.f;
    #pragma unroll
    for (int nt = 0; nt < 10; nt++) {
        e[nt][0] = __expf(fmaf(s[nt][0], scale, -ms0));
        e[nt][1] = __expf(fmaf(s[nt][1], scale, -ms0));
        e[nt][2] = __expf(fmaf(s[nt][2], scale, -ms1));
        e[nt][3] = __expf(fmaf(s[nt][3], scale, -ms1));
        sum0 += e[nt][0] + e[nt][1];
        sum1 += e[nt][2] + e[nt][3];
    }
    sum0 += __shfl_xor_sync(0xffffffff, sum0, 1);
    sum0 += __shfl_xor_sync(0xffffffff, sum0, 2);
    sum1 += __shfl_xor_sync(0xffffffff, sum1, 1);
    sum1 += __shfl_xor_sync(0xffffffff, sum1, 2);
    float inv0 = 1.0f / sum0, inv1 = 1.0f / sum1;

    uint32_t pa[5][4];
    #pragma unroll
    for (int kf = 0; kf < 5; kf++) {
        pa[kf][0] = packbf(e[2 * kf][0],     e[2 * kf][1]);
        pa[kf][1] = packbf(e[2 * kf][2],     e[2 * kf][3]);
        pa[kf][2] = packbf(e[2 * kf + 1][0], e[2 * kf + 1][1]);
        pa[kf][3] = packbf(e[2 * kf + 1][2], e[2 * kf + 1][3]);
    }

    float oa[4][4] = {};
    #pragma unroll
    for (int kf = 0; kf < 5; kf++) {
        #pragma unroll
        for (int vt = 0; vt < 2; vt++) {
            uint32_t b[4];
            ldsm4t(b, bV + (kf * 16 * 40 + vt * 16) * 2);
            mma_bf16(oa[2 * vt],     pa[kf], b[0], b[1]);
            mma_bf16(oa[2 * vt + 1], pa[kf], b[2], b[3]);
        }
    }

    int r0 = w * 16 + g, r1 = r0 + 8;
    if (r0 < L77) {
        int grow = rowmap(wi, r0);
        size_t base = ((size_t)((grow >> 7) * 4 + (h >> 1))) * 8192 + (grow & 127) * 64;
        int rk = grow & 7;
        #pragma unroll
        for (int nt = 0; nt < 4; nt++) {
            int ci = ((h & 1) * 4 + nt) ^ rk;
            *(uint32_t*)&o[base + ci * 8 + 2 * t] =
                packbf(oa[nt][0] * inv0, oa[nt][1] * inv0);
        }
    }
    if (r1 < L77) {
        int grow = rowmap(wi, r1);
        size_t base = ((size_t)((grow >> 7) * 4 + (h >> 1))) * 8192 + (grow & 127) * 64;
        int rk = grow & 7;
        #pragma unroll
        for (int nt = 0; nt < 4; nt++) {
            int ci = ((h & 1) * 4 + nt) ^ rk;
            *(uint32_t*)&o[base + ci * 8 + 2 * t] =
                packbf(oa[nt][2] * inv1, oa[nt][3] * inv1);
        }
    }
}

// ---------------------------------------------------------------------------
// Launch
// ---------------------------------------------------------------------------
extern "C" void kernel_launch(void* const* d_in, const int* in_sizes, int n_in,
                              void* d_out, int out_size)
{
    const float* x         = (const float*)d_in[0];
    const float* norm1_g   = (const float*)d_in[1];
    const float* norm1_b   = (const float*)d_in[2];
    const float* in_proj_w = (const float*)d_in[3];
    const float* in_proj_b = (const float*)d_in[4];
    const float* out_w     = (const float*)d_in[5];
    const float* out_b     = (const float*)d_in[6];
    const float* norm2_g   = (const float*)d_in[7];
    const float* norm2_b   = (const float*)d_in[8];
    const float* fc1_w     = (const float*)d_in[9];
    const float* fc1_b     = (const float*)d_in[10];
    const float* fc2_w     = (const float*)d_in[11];
    const float* fc2_b     = (const float*)d_in[12];
    float* out = (float*)d_out;

    __nv_bfloat16 *p_xnb, *p_qkvb, *p_wqkv, *p_wout, *p_wfc1, *p_wfc2;
    float* p_y;
    cudaGetSymbolAddress((void**)&p_xnb,  g_xnb);
    cudaGetSymbolAddress((void**)&p_qkvb, g_qkvb);
    cudaGetSymbolAddress((void**)&p_y,    g_y);
    cudaGetSymbolAddress((void**)&p_wqkv, g_wqkv);
    cudaGetSymbolAddress((void**)&p_wout, g_wout);
    cudaGetSymbolAddress((void**)&p_wfc1, g_wfc1);
    cudaGetSymbolAddress((void**)&p_wfc2, g_wfc2);

    cudaFuncSetAttribute((const void*)bgemm_kernel<0, 1, 256, 0, 0>,
                         cudaFuncAttributeMaxDynamicSharedMemorySize, BGSMEM);
    cudaFuncSetAttribute((const void*)bgemm_kernel<2, 0, 256, 0, 0>,
                         cudaFuncAttributeMaxDynamicSharedMemorySize, BGSMEM);
    cudaFuncSetAttribute((const void*)bgemm_kernel<1, 1, 256, 1, 8>,
                         cudaFuncAttributeMaxDynamicSharedMemorySize, BGSMEM);
    cudaFuncSetAttribute((const void*)bgemm_kernel<2, 0, 512, 0, 0>,
                         cudaFuncAttributeMaxDynamicSharedMemorySize, BGSMEM);

    // 0+1) weights -> tiled bf16 images AND LN1 (merged)
    prep_kernel<<<256 + MROWS / 8, 256>>>(x, norm1_g, norm1_b, p_xnb,
                                          in_proj_w, out_w, fc1_w, fc2_w,
                                          p_wqkv, p_wout, p_wfc1, p_wfc2);

    // 2) QKV = xn @ Wqkv^T + b  (row-major bf16)
    {
        dim3 grid(768 / 128, MROWS / 128);
        bgemm_kernel<0, 1, 256, 0, 0><<<grid, 256, BGSMEM>>>(
            p_xnb, p_wqkv, in_proj_b, nullptr, p_qkvb, MROWS, 3 * Dc);
    }

    // 3) attention -> o image (reuse g_xnb)
    attn_kernel<<<NWIN * HEADS, 160>>>(p_qkvb, p_xnb);

    // 4) y = x + o @ Wout^T + b  (fp32 row-major)
    {
        dim3 grid(Dc / 128, MROWS / 128);
        bgemm_kernel<2, 0, 256, 0, 0><<<grid, 256, BGSMEM>>>(
            p_xnb, p_wout, out_b, x, p_y, MROWS, Dc);
    }

    // 5) LN2: y -> yn image (into g_qkvb[0 : M*256))
    ln_bf_kernel<<<MROWS / 8, 256>>>(p_y, norm2_g, norm2_b, p_qkvb);

    // 6) hmid = gelu(yn @ Wfc1^T + b)  (tiled image, OKT=8)
    __nv_bfloat16* p_yn   = p_qkvb;
    __nv_bfloat16* p_hmid = p_qkvb + (size_t)MROWS * Dc;
    {
        dim3 grid(HIDc / 128, MROWS / 128);
        bgemm_kernel<1, 1, 256, 1, 8><<<grid, 256, BGSMEM>>>(
            p_yn, p_wfc1, fc1_b, nullptr, p_hmid, MROWS, HIDc);
    }

    // 7) out = y + hmid @ Wfc2^T + b  (fp32 row-major)
    {
        dim3 grid(Dc / 128, MROWS / 128);
        bgemm_kernel<2, 0, 512, 0, 0><<<grid, 256, BGSMEM>>>(
            p_hmid, p_wfc2, fc2_b, p_y, out, MROWS, Dc);
    }
}